// round 10
// baseline (speedup 1.0000x reference)
#include <cuda_runtime.h>
#include <cuda_bf16.h>
#include <stdint.h>
#include <math.h>

// ---------------------------------------------------------------------------
// MultiheadDiffAttn (B=2, N=2048, E=1024, H=8, D=64, depth=12)
// bf16 hi/lo 3-term mma.sync (m16n8k16, fp32 accum) for all GEMMs.
// R10: S stored as bf16 hi/lo (halves scores-store + softmax-read traffic),
//      single-sync 3-stage pipelines.
// ---------------------------------------------------------------------------

#define Bb 2
#define Nq 2048
#define Ee 1024
#define Hh 8
#define Mtok 4096

__device__ __align__(16) __nv_bfloat16 g_xh[Mtok * Ee];
__device__ __align__(16) __nv_bfloat16 g_xl[Mtok * Ee];
__device__ __align__(16) __nv_bfloat16 g_wth[4][Ee * Ee];
__device__ __align__(16) __nv_bfloat16 g_wtl[4][Ee * Ee];
__device__ __align__(16) __nv_bfloat16 g_qh[Bb * 16 * Nq * 64];
__device__ __align__(16) __nv_bfloat16 g_ql[Bb * 16 * Nq * 64];
__device__ __align__(16) __nv_bfloat16 g_kh[Bb * 16 * Nq * 64];
__device__ __align__(16) __nv_bfloat16 g_kl[Bb * 16 * Nq * 64];
__device__ __align__(16) __nv_bfloat16 g_vnh[Bb * Hh * Nq * 128];
__device__ __align__(16) __nv_bfloat16 g_vnl[Bb * Hh * Nq * 128];
__device__ __align__(16) __nv_bfloat16 g_vth[Bb * Hh * 128 * Nq];
__device__ __align__(16) __nv_bfloat16 g_vtl[Bb * Hh * 128 * Nq];
__device__ __align__(16) __nv_bfloat16 g_Sh[(size_t)Bb * 16 * Nq * Nq];  // scores hi
__device__ __align__(16) __nv_bfloat16 g_Sl[(size_t)Bb * 16 * Nq * Nq];  // scores lo
__device__ __align__(16) __nv_bfloat16 g_Wh[(size_t)Bb * Hh * Nq * Nq];
__device__ __align__(16) __nv_bfloat16 g_Wl[(size_t)Bb * Hh * Nq * Nq];
__device__ __align__(16) __nv_bfloat16 g_oh[Mtok * Ee];
__device__ __align__(16) __nv_bfloat16 g_ol[Mtok * Ee];
__device__ float g_lambda;

__device__ __forceinline__ uint32_t smem_to_u32(const void* p) {
    uint32_t a;
    asm("{ .reg .u64 t; cvta.to.shared.u64 t, %1; cvt.u32.u64 %0, t; }" : "=r"(a) : "l"(p));
    return a;
}
__device__ __forceinline__ void ldsm_x4(uint32_t addr, uint32_t* r) {
    asm volatile("ldmatrix.sync.aligned.m8n8.x4.shared.b16 {%0,%1,%2,%3}, [%4];"
                 : "=r"(r[0]), "=r"(r[1]), "=r"(r[2]), "=r"(r[3]) : "r"(addr));
}
__device__ __forceinline__ void mma_bf16(float* c, const uint32_t* a, const uint32_t* b) {
    asm volatile(
        "mma.sync.aligned.m16n8k16.row.col.f32.bf16.bf16.f32 "
        "{%0,%1,%2,%3}, {%4,%5,%6,%7}, {%8,%9}, {%0,%1,%2,%3};"
        : "+f"(c[0]), "+f"(c[1]), "+f"(c[2]), "+f"(c[3])
        : "r"(a[0]), "r"(a[1]), "r"(a[2]), "r"(a[3]), "r"(b[0]), "r"(b[1]));
}
template <int RB>
__device__ __forceinline__ void ldA(uint32_t tile, int mo, int kb, int lane, uint32_t* r) {
    int row = mo + (lane & 15);
    int cb = kb + ((lane >> 4) << 4);
    uint32_t off = (uint32_t)(row * RB + cb);
    ldsm_x4(tile + (off ^ ((off >> 3) & 0x70)), r);
}
template <int RB>
__device__ __forceinline__ void ldB(uint32_t tile, int no, int kb, int lane, uint32_t* r) {
    int row = no + ((lane >> 4) << 3) + (lane & 7);
    int cb = kb + (((lane >> 3) & 1) << 4);
    uint32_t off = (uint32_t)(row * RB + cb);
    ldsm_x4(tile + (off ^ ((off >> 3) & 0x70)), r);
}
#define CP_COMMIT() asm volatile("cp.async.commit_group;" ::: "memory")
#define CP_WAIT(n)  asm volatile("cp.async.wait_group %0;" :: "n"(n) : "memory")

template <int R>
__device__ __forceinline__ void cp_tile32(uint32_t dst, const __nv_bfloat16* src,
                                          size_t ld, int tid) {
    #pragma unroll
    for (int i = tid; i < R * 4; i += 256) {
        int r = i >> 2, c8 = i & 3;
        uint32_t off = (uint32_t)((r << 6) | (c8 << 4));
        const void* g = src + (size_t)r * ld + c8 * 8;
        asm volatile("cp.async.cg.shared.global [%0], [%1], 16;"
                     :: "r"(dst + (off ^ ((off >> 3) & 0x70))), "l"(g) : "memory");
    }
}
template <int R>
__device__ __forceinline__ void cp_tile64(uint32_t dst, const __nv_bfloat16* src,
                                          size_t ld, int tid) {
    #pragma unroll
    for (int i = tid; i < R * 8; i += 256) {
        int r = i >> 3, c8 = i & 7;
        uint32_t off = (uint32_t)((r << 7) | (c8 << 4));
        const void* g = src + (size_t)r * ld + c8 * 8;
        asm volatile("cp.async.cg.shared.global [%0], [%1], 16;"
                     :: "r"(dst + (off ^ ((off >> 3) & 0x70))), "l"(g) : "memory");
    }
}
__device__ __forceinline__ void split2(float a, float b, uint32_t& hp, uint32_t& lp) {
    __nv_bfloat16 h0 = __float2bfloat16(a), h1 = __float2bfloat16(b);
    __nv_bfloat16 l0 = __float2bfloat16(a - __bfloat162float(h0));
    __nv_bfloat16 l1 = __float2bfloat16(b - __bfloat162float(h1));
    hp = (uint32_t)__bfloat16_as_ushort(h0) | ((uint32_t)__bfloat16_as_ushort(h1) << 16);
    lp = (uint32_t)__bfloat16_as_ushort(l0) | ((uint32_t)__bfloat16_as_ushort(l1) << 16);
}

// ---------------------------------------------------------------------------
__global__ void lambda_kernel(const float* lq1, const float* lk1,
                              const float* lq2, const float* lk2) {
    int t = threadIdx.x;
    float s1 = lq1[t] * lk1[t] + lq1[t + 32] * lk1[t + 32];
    float s2 = lq2[t] * lk2[t] + lq2[t + 32] * lk2[t + 32];
    #pragma unroll
    for (int o = 16; o; o >>= 1) {
        s1 += __shfl_xor_sync(0xFFFFFFFFu, s1, o);
        s2 += __shfl_xor_sync(0xFFFFFFFFu, s2, o);
    }
    if (t == 0) {
        float lam_init = 0.8f - 0.6f * expf(-0.3f * 12.0f);
        g_lambda = expf(s1) - expf(s2) + lam_init;
    }
}

__global__ void __launch_bounds__(256) convert_x(const float* __restrict__ x) {
    size_t i = ((size_t)blockIdx.x * 256 + threadIdx.x) * 4;
    float4 v = *(const float4*)(x + i);
    uint32_t h0, l0, h1, l1;
    split2(v.x, v.y, h0, l0);
    split2(v.z, v.w, h1, l1);
    *(uint2*)(g_xh + i) = make_uint2(h0, h1);
    *(uint2*)(g_xl + i) = make_uint2(l0, l1);
}

__global__ void transpose_w(const float* W0, const float* W1,
                            const float* W2, const float* W3) {
    __shared__ float t[32][33];
    int zi = blockIdx.z;
    const float* W = (zi == 0) ? W0 : (zi == 1) ? W1 : (zi == 2) ? W2 : W3;
    __nv_bfloat16* Th = g_wth[zi];
    __nv_bfloat16* Tl = g_wtl[zi];
    int n0 = blockIdx.x * 32, k0 = blockIdx.y * 32;
    int tx = threadIdx.x, ty = threadIdx.y;
    #pragma unroll
    for (int rr = 0; rr < 4; rr++)
        t[ty + 8 * rr][tx] = W[(size_t)(k0 + ty + 8 * rr) * 1024 + n0 + tx];
    __syncthreads();
    #pragma unroll
    for (int rr = 0; rr < 4; rr++) {
        float v = t[tx][ty + 8 * rr];
        __nv_bfloat16 hi = __float2bfloat16(v);
        __nv_bfloat16 lo = __float2bfloat16(v - __bfloat162float(hi));
        size_t o = (size_t)(n0 + ty + 8 * rr) * 1024 + k0 + tx;
        Th[o] = hi;
        Tl[o] = lo;
    }
}

__global__ void vtrans_kernel() {
    __shared__ __nv_bfloat16 th[32][33], tl[32][33];
    int z = blockIdx.z, n0 = blockIdx.x * 32, c0 = blockIdx.y * 32;
    int tx = threadIdx.x, ty = threadIdx.y;
    #pragma unroll
    for (int rr = 0; rr < 4; rr++) {
        size_t s = ((size_t)z * 2048 + n0 + ty + 8 * rr) * 128 + c0 + tx;
        th[ty + 8 * rr][tx] = g_vnh[s];
        tl[ty + 8 * rr][tx] = g_vnl[s];
    }
    __syncthreads();
    #pragma unroll
    for (int rr = 0; rr < 4; rr++) {
        size_t d = ((size_t)z * 128 + c0 + ty + 8 * rr) * 2048 + n0 + tx;
        g_vth[d] = th[tx][ty + 8 * rr];
        g_vtl[d] = tl[tx][ty + 8 * rr];
    }
}

// ---------------------------------------------------------------------------
#define BSTG 32768
__global__ void __launch_bounds__(256, 2) gemm_big(int mode_sel, float* __restrict__ dout) {
    extern __shared__ __align__(1024) char sm[];
    const int tid = threadIdx.x, wid = tid >> 5, lane = tid & 31;
    const int gid = lane >> 2, tg = lane & 3;
    const int mode = (mode_sel < 0) ? (int)blockIdx.z : mode_sel;
    uint32_t t0 = (smem_to_u32(sm) + 1023) & ~1023u;

    const int m0 = blockIdx.y * 128, n0 = blockIdx.x * 128;
    const __nv_bfloat16* Agh = ((mode == 3) ? g_oh : g_xh) + (size_t)m0 * 1024;
    const __nv_bfloat16* Agl = ((mode == 3) ? g_ol : g_xl) + (size_t)m0 * 1024;
    const __nv_bfloat16* Bgh = g_wth[mode] + (size_t)n0 * 1024;
    const __nv_bfloat16* Bgl = g_wtl[mode] + (size_t)n0 * 1024;

    const int mw = (wid >> 1) * 32, nw = (wid & 1) * 64;
    float acc[2][8][4];
    #pragma unroll
    for (int i = 0; i < 2; i++)
        #pragma unroll
        for (int j = 0; j < 8; j++)
            #pragma unroll
            for (int r = 0; r < 4; r++) acc[i][j][r] = 0.f;

    auto issue = [&](int st, int c) {
        uint32_t s = t0 + st * BSTG;
        cp_tile32<128>(s,         Agh + c * 32, 1024, tid);
        cp_tile32<128>(s + 8192,  Agl + c * 32, 1024, tid);
        cp_tile32<128>(s + 16384, Bgh + c * 32, 1024, tid);
        cp_tile32<128>(s + 24576, Bgl + c * 32, 1024, tid);
        CP_COMMIT();
    };
    const int NC = 32;
    issue(0, 0);
    issue(1, 1);
    #pragma unroll 1
    for (int c = 0; c < NC; c++) {
        if (c + 1 < NC) CP_WAIT(1);
        else CP_WAIT(0);
        __syncthreads();
        if (c + 2 < NC) issue((c + 2) % 3, c + 2);
        uint32_t s = t0 + (c % 3) * BSTG;
        uint32_t Ah = s, Al = s + 8192, Bh = s + 16384, Bl = s + 24576;
        #pragma unroll
        for (int ks = 0; ks < 2; ks++) {
            int kb = ks * 32;
            uint32_t ah[2][4], al[2][4];
            #pragma unroll
            for (int am = 0; am < 2; am++) {
                ldA<64>(Ah, mw + am * 16, kb, lane, ah[am]);
                ldA<64>(Al, mw + am * 16, kb, lane, al[am]);
            }
            #pragma unroll
            for (int bn = 0; bn < 4; bn++) {
                uint32_t bh[4], bl[4];
                ldB<64>(Bh, nw + bn * 16, kb, lane, bh);
                ldB<64>(Bl, nw + bn * 16, kb, lane, bl);
                #pragma unroll
                for (int am = 0; am < 2; am++)
                    #pragma unroll
                    for (int sub = 0; sub < 2; sub++) {
                        float* a = acc[am][bn * 2 + sub];
                        mma_bf16(a, ah[am], &bh[sub * 2]);
                        mma_bf16(a, ah[am], &bl[sub * 2]);
                        mma_bf16(a, al[am], &bh[sub * 2]);
                    }
            }
        }
    }

    #pragma unroll
    for (int am = 0; am < 2; am++) {
        int r0 = m0 + mw + am * 16 + gid;
        #pragma unroll
        for (int an = 0; an < 8; an++) {
            int gc = n0 + nw + an * 8 + tg * 2;
            float* a = acc[am][an];
            if (mode == 3) {
                *(float2*)(dout + (size_t)r0 * 1024 + gc) = make_float2(a[0], a[1]);
                *(float2*)(dout + (size_t)(r0 + 8) * 1024 + gc) = make_float2(a[2], a[3]);
            } else {
                float sc = (mode == 0) ? 0.125f : 1.f;
                #pragma unroll
                for (int rp = 0; rp < 2; rp++) {
                    int gm = r0 + rp * 8, bb = gm >> 11, nn = gm & 2047;
                    uint32_t hp, lp;
                    split2(a[rp * 2] * sc, a[rp * 2 + 1] * sc, hp, lp);
                    size_t di;
                    __nv_bfloat16 *Dh, *Dl;
                    if (mode == 2) {
                        int h = gc >> 7, ch = gc & 127;
                        di = ((size_t)((bb * 8 + h) * 2048 + nn)) * 128 + ch;
                        Dh = g_vnh; Dl = g_vnl;
                    } else {
                        int hh = gc >> 6, d = gc & 63;
                        di = ((size_t)((bb * 16 + hh) * 2048 + nn)) * 64 + d;
                        Dh = (mode == 0) ? g_qh : g_kh;
                        Dl = (mode == 0) ? g_ql : g_kl;
                    }
                    *(uint32_t*)(Dh + di) = hp;
                    *(uint32_t*)(Dl + di) = lp;
                }
            }
        }
    }
}

// ---------------------------------------------------------------------------
// Scores: S[z] = Q[z] @ K[z]^T -> bf16 hi/lo
__global__ void __launch_bounds__(256, 2) gemm_scores() {
    extern __shared__ __align__(1024) char sm[];
    const int tid = threadIdx.x, wid = tid >> 5, lane = tid & 31;
    const int gid = lane >> 2, tg = lane & 3;
    uint32_t t0 = (smem_to_u32(sm) + 1023) & ~1023u;

    int z = blockIdx.z, m0 = blockIdx.y * 128, n0 = blockIdx.x * 128;
    cp_tile64<128>(t0,         g_qh + ((size_t)z * 2048 + m0) * 64, 64, tid);
    cp_tile64<128>(t0 + 16384, g_ql + ((size_t)z * 2048 + m0) * 64, 64, tid);
    cp_tile64<128>(t0 + 32768, g_kh + ((size_t)z * 2048 + n0) * 64, 64, tid);
    cp_tile64<128>(t0 + 49152, g_kl + ((size_t)z * 2048 + n0) * 64, 64, tid);
    CP_COMMIT();
    CP_WAIT(0);
    __syncthreads();

    const int mw = (wid >> 1) * 32, nw = (wid & 1) * 64;
    float acc[2][8][4];
    #pragma unroll
    for (int i = 0; i < 2; i++)
        #pragma unroll
        for (int j = 0; j < 8; j++)
            #pragma unroll
            for (int r = 0; r < 4; r++) acc[i][j][r] = 0.f;

    uint32_t Ah = t0, Al = t0 + 16384, Bh = t0 + 32768, Bl = t0 + 49152;
    #pragma unroll
    for (int ks = 0; ks < 4; ks++) {
        int kb = ks * 32;
        uint32_t ah[2][4], al[2][4];
        #pragma unroll
        for (int am = 0; am < 2; am++) {
            ldA<128>(Ah, mw + am * 16, kb, lane, ah[am]);
            ldA<128>(Al, mw + am * 16, kb, lane, al[am]);
        }
        #pragma unroll
        for (int bn = 0; bn < 4; bn++) {
            uint32_t bh[4], bl[4];
            ldB<128>(Bh, nw + bn * 16, kb, lane, bh);
            ldB<128>(Bl, nw + bn * 16, kb, lane, bl);
            #pragma unroll
            for (int am = 0; am < 2; am++)
                #pragma unroll
                for (int sub = 0; sub < 2; sub++) {
                    float* a = acc[am][bn * 2 + sub];
                    mma_bf16(a, ah[am], &bh[sub * 2]);
                    mma_bf16(a, ah[am], &bl[sub * 2]);
                    mma_bf16(a, al[am], &bh[sub * 2]);
                }
        }
    }

    __nv_bfloat16* Ch = g_Sh + ((size_t)z * 2048 + m0) * 2048 + n0;
    __nv_bfloat16* Cl = g_Sl + ((size_t)z * 2048 + m0) * 2048 + n0;
    #pragma unroll
    for (int am = 0; am < 2; am++) {
        int r0 = mw + am * 16 + gid;
        #pragma unroll
        for (int an = 0; an < 8; an++) {
            int gc = nw + an * 8 + tg * 2;
            float* a = acc[am][an];
            uint32_t hp, lp;
            split2(a[0], a[1], hp, lp);
            *(uint32_t*)(Ch + (size_t)r0 * 2048 + gc) = hp;
            *(uint32_t*)(Cl + (size_t)r0 * 2048 + gc) = lp;
            split2(a[2], a[3], hp, lp);
            *(uint32_t*)(Ch + (size_t)(r0 + 8) * 2048 + gc) = hp;
            *(uint32_t*)(Cl + (size_t)(r0 + 8) * 2048 + gc) = lp;
        }
    }
}

// ---------------------------------------------------------------------------
// Softmax pair + lambda combine; reads bf16 hi/lo S, writes bf16 hi/lo W.
__global__ void __launch_bounds__(256) softmax_kernel() {
    int q = blockIdx.x, h = blockIdx.y, b = blockIdx.z;
    float lam = g_lambda;
    size_t o1 = ((size_t)(b * 16 + 2 * h)) * Nq * Nq + (size_t)q * Nq;
    size_t o2 = o1 + (size_t)Nq * Nq;
    __nv_bfloat16* wh = g_Wh + ((size_t)(b * 8 + h) * 2048 + q) * 2048;
    __nv_bfloat16* wl = g_Wl + ((size_t)(b * 8 + h) * 2048 + q) * 2048;

    int tid = threadIdx.x;
    int base = tid * 8;
    float v1[8], v2[8], m1 = -1e30f, m2 = -1e30f;
    {
        uint4 h1v = *(const uint4*)(g_Sh + o1 + base);
        uint4 l1v = *(const uint4*)(g_Sl + o1 + base);
        uint4 h2v = *(const uint4*)(g_Sh + o2 + base);
        uint4 l2v = *(const uint4*)(g_Sl + o2 + base);
        const uint32_t* hp1 = &h1v.x;
        const uint32_t* lp1 = &l1v.x;
        const uint32_t* hp2 = &h2v.x;
        const uint32_t* lp2 = &l2v.x;
        #pragma unroll
        for (int i = 0; i < 4; i++) {
            float2 hh = __bfloat1622float2(*(const __nv_bfloat162*)&hp1[i]);
            float2 ll = __bfloat1622float2(*(const __nv_bfloat162*)&lp1[i]);
            v1[2 * i] = hh.x + ll.x;
            v1[2 * i + 1] = hh.y + ll.y;
            hh = __bfloat1622float2(*(const __nv_bfloat162*)&hp2[i]);
            ll = __bfloat1622float2(*(const __nv_bfloat162*)&lp2[i]);
            v2[2 * i] = hh.x + ll.x;
            v2[2 * i + 1] = hh.y + ll.y;
        }
    }
    #pragma unroll
    for (int i = 0; i < 8; i++) { m1 = fmaxf(m1, v1[i]); m2 = fmaxf(m2, v2[i]); }

    __shared__ float red1[8], red2[8], su1[8], su2[8];
    #pragma unroll
    for (int o = 16; o; o >>= 1) {
        m1 = fmaxf(m1, __shfl_xor_sync(0xFFFFFFFFu, m1, o));
        m2 = fmaxf(m2, __shfl_xor_sync(0xFFFFFFFFu, m2, o));
    }
    int warp = tid >> 5, lane = tid & 31;
    if (lane == 0) { red1[warp] = m1; red2[warp] = m2; }
    __syncthreads();
    m1 = red1[0]; m2 = red2[0];
    #pragma unroll
    for (int w = 1; w < 8; w++) { m1 = fmaxf(m1, red1[w]); m2 = fmaxf(m2, red2[w]); }
    float l1 = 0.f, l2 = 0.f;
    #pragma unroll
    for (int i = 0; i < 8; i++) {
        v1[i] = __expf(v1[i] - m1); l1 += v1[i];
        v2[i] = __expf(v2[i] - m2); l2 += v2[i];
    }
    #pragma unroll
    for (int o = 16; o; o >>= 1) {
        l1 += __shfl_xor_sync(0xFFFFFFFFu, l1, o);
        l2 += __shfl_xor_sync(0xFFFFFFFFu, l2, o);
    }
    if (lane == 0) { su1[warp] = l1; su2[warp] = l2; }
    __syncthreads();
    l1 = su1[0]; l2 = su2[0];
    #pragma unroll
    for (int w = 1; w < 8; w++) { l1 += su1[w]; l2 += su2[w]; }
    float inv1 = 1.f / l1, inv2 = lam / l2;

    uint32_t hp[4], lp[4];
    #pragma unroll
    for (int i = 0; i < 4; i++) {
        float w0 = v1[2 * i] * inv1 - v2[2 * i] * inv2;
        float w1 = v1[2 * i + 1] * inv1 - v2[2 * i + 1] * inv2;
        split2(w0, w1, hp[i], lp[i]);
    }
    *(uint4*)(wh + base) = make_uint4(hp[0], hp[1], hp[2], hp[3]);
    *(uint4*)(wl + base) = make_uint4(lp[0], lp[1], lp[2], lp[3]);
}

// ---------------------------------------------------------------------------
#define PSTG 24576
__global__ void __launch_bounds__(256, 2) gemm_pv(const float* __restrict__ lng,
                                                  const float* __restrict__ lnb) {
    extern __shared__ __align__(1024) char sm[];
    const int tid = threadIdx.x, wid = tid >> 5, lane = tid & 31;
    const int gid = lane >> 2, tg = lane & 3;
    uint32_t t0 = (smem_to_u32(sm) + 1023) & ~1023u;

    int z = blockIdx.z, b = z >> 3, h = z & 7, m0 = blockIdx.y * 64;
    const __nv_bfloat16* Agh = g_Wh + ((size_t)z * 2048 + m0) * 2048;
    const __nv_bfloat16* Agl = g_Wl + ((size_t)z * 2048 + m0) * 2048;
    const __nv_bfloat16* Bgh = g_vth + (size_t)z * 128 * 2048;
    const __nv_bfloat16* Bgl = g_vtl + (size_t)z * 128 * 2048;

    const int mw = (wid >> 1) * 16, nw = (wid & 1) * 64;
    float acc[8][4];
    #pragma unroll
    for (int j = 0; j < 8; j++)
        #pragma unroll
        for (int r = 0; r < 4; r++) acc[j][r] = 0.f;

    auto issue = [&](int st, int c) {
        uint32_t s = t0 + st * PSTG;
        cp_tile32<64>(s,          Agh + c * 32, 2048, tid);
        cp_tile32<64>(s + 4096,   Agl + c * 32, 2048, tid);
        cp_tile32<128>(s + 8192,  Bgh + c * 32, 2048, tid);
        cp_tile32<128>(s + 16384, Bgl + c * 32, 2048, tid);
        CP_COMMIT();
    };
    const int NC = 64;
    issue(0, 0);
    issue(1, 1);
    #pragma unroll 1
    for (int c = 0; c < NC; c++) {
        if (c + 1 < NC) CP_WAIT(1);
        else CP_WAIT(0);
        __syncthreads();
        if (c + 2 < NC) issue((c + 2) % 3, c + 2);
        uint32_t s = t0 + (c % 3) * PSTG;
        uint32_t Ah = s, Al = s + 4096, Bh = s + 8192, Bl = s + 16384;
        #pragma unroll
        for (int ks = 0; ks < 2; ks++) {
            int kb = ks * 32;
            uint32_t ah[4], al[4];
            ldA<64>(Ah, mw, kb, lane, ah);
            ldA<64>(Al, mw, kb, lane, al);
            #pragma unroll
            for (int bn = 0; bn < 4; bn++) {
                uint32_t bh[4], bl[4];
                ldB<64>(Bh, nw + bn * 16, kb, lane, bh);
                ldB<64>(Bl, nw + bn * 16, kb, lane, bl);
                #pragma unroll
                for (int sub = 0; sub < 2; sub++) {
                    float* a = acc[bn * 2 + sub];
                    mma_bf16(a, ah, &bh[sub * 2]);
                    mma_bf16(a, ah, &bl[sub * 2]);
                    mma_bf16(a, al, &bh[sub * 2]);
                }
            }
        }
    }
    __syncthreads();

    float* stg = (float*)(sm + (t0 - smem_to_u32(sm)));
    const int LD = 132;
    #pragma unroll
    for (int an = 0; an < 8; an++) {
        int col = nw + an * 8 + tg * 2;
        stg[(mw + gid) * LD + col] = acc[an][0];
        stg[(mw + gid) * LD + col + 1] = acc[an][1];
        stg[(mw + gid + 8) * LD + col] = acc[an][2];
        stg[(mw + gid + 8) * LD + col + 1] = acc[an][3];
    }
    __syncthreads();

    #pragma unroll 1
    for (int rr = 0; rr < 8; rr++) {
        int r = wid * 8 + rr;
        float x0 = stg[r * LD + lane], x1 = stg[r * LD + lane + 32];
        float x2 = stg[r * LD + lane + 64], x3 = stg[r * LD + lane + 96];
        float s = x0 + x1 + x2 + x3;
        float ss = x0 * x0 + x1 * x1 + x2 * x2 + x3 * x3;
        #pragma unroll
        for (int o = 16; o; o >>= 1) {
            s  += __shfl_xor_sync(0xFFFFFFFFu, s, o);
            ss += __shfl_xor_sync(0xFFFFFFFFu, ss, o);
        }
        float mean = s * (1.f / 128.f);
        float var = ss * (1.f / 128.f) - mean * mean;
        float rstd = rsqrtf(var + 1e-5f);
        size_t base = ((size_t)(b * 2048 + m0 + r)) * 1024 + h * 128;
        float xv[4] = {x0, x1, x2, x3};
        #pragma unroll
        for (int j = 0; j < 4; j++) {
            int c = lane + 32 * j;
            float w = (xv[j] - mean) * rstd * lng[c] + lnb[c];
            __nv_bfloat16 hi = __float2bfloat16(w);
            __nv_bfloat16 lo = __float2bfloat16(w - __bfloat162float(hi));
            g_oh[base + c] = hi;
            g_ol[base + c] = lo;
        }
    }
}

// ---------------------------------------------------------------------------
extern "C" void kernel_launch(void* const* d_in, const int* in_sizes, int n_in,
                              void* d_out, int out_size) {
    const float* x   = (const float*)d_in[0];
    const float* Wq  = (const float*)d_in[1];
    const float* Wk  = (const float*)d_in[2];
    const float* Wv  = (const float*)d_in[3];
    const float* Wo  = (const float*)d_in[4];
    const float* lq1 = (const float*)d_in[5];
    const float* lk1 = (const float*)d_in[6];
    const float* lq2 = (const float*)d_in[7];
    const float* lk2 = (const float*)d_in[8];
    const float* lng = (const float*)d_in[9];
    const float* lnb = (const float*)d_in[10];
    float* out = (float*)d_out;

    const int SM_BIG = 3 * BSTG + 1024;   // 99328  -> 2 CTAs/SM
    const int SM_SC  = 65536 + 1024;      // 66560  -> 2 CTAs/SM
    const int SM_PV  = 3 * PSTG + 1024;   // 74752  -> 2 CTAs/SM
    cudaFuncSetAttribute(gemm_big, cudaFuncAttributeMaxDynamicSharedMemorySize, SM_BIG);
    cudaFuncSetAttribute(gemm_scores, cudaFuncAttributeMaxDynamicSharedMemorySize, SM_SC);
    cudaFuncSetAttribute(gemm_pv, cudaFuncAttributeMaxDynamicSharedMemorySize, SM_PV);

    lambda_kernel<<<1, 32>>>(lq1, lk1, lq2, lk2);
    convert_x<<<4096, 256>>>(x);
    transpose_w<<<dim3(32, 32, 4), dim3(32, 8)>>>(Wq, Wk, Wv, Wo);

    gemm_big<<<dim3(8, 32, 3), 256, SM_BIG>>>(-1, nullptr);   // q,k,v projections
    vtrans_kernel<<<dim3(64, 4, 16), dim3(32, 8)>>>();
    gemm_scores<<<dim3(16, 16, 32), 256, SM_SC>>>();
    softmax_kernel<<<dim3(2048, 8, 2), 256>>>();
    gemm_pv<<<dim3(1, 32, 16), 256, SM_PV>>>(lng, lnb);
    gemm_big<<<dim3(8, 32, 1), 256, SM_BIG>>>(3, out);        // output projection
}